// round 3
// baseline (speedup 1.0000x reference)
#include <cuda_runtime.h>

// Problem constants (hardcoded from reference)
#define BATCH 4
#define HEADS 8
#define LSEQ  2048
#define DKK   32
#define DVV   32
#define BHN   (BATCH*HEADS)

#define BM    64     // q rows per CTA
#define BN    64     // k cols per tile
#define NTH   256
#define PITCH 68     // smem pitch (floats), 16B-aligned, conflict-mitigating

__global__ __launch_bounds__(NTH)
void attn_fused_kernel(const float* __restrict__ Q,
                       const float* __restrict__ K,
                       const float* __restrict__ V,
                       const int* __restrict__ Mk,     // bool marshalled as int32
                       const float* __restrict__ Rs,
                       float* __restrict__ out_ctx,
                       float* __restrict__ out_sc)
{
    __shared__ float QsT[DKK][PITCH];   // Q transposed: [d][row]
    __shared__ float KsT[DKK][PITCH];   // K transposed: [d][col]
    __shared__ float Vs[BN][DVV];       // V natural:    [n][dv]
    __shared__ float Ps[BM][PITCH];     // softmax P:    [row][n]

    const int t  = threadIdx.x;
    const int bh = blockIdx.y;
    const int q0 = blockIdx.x * BM;

    const int cg  = t & 15;     // col group 0..15
    const int rg  = t >> 4;     // row group 0..15
    const int c0  = cg * 4;     // S cols (4 consecutive)
    const int r0  = rg * 4;     // S rows (4 consecutive)
    const int cc0 = cg * 2;     // context cols (2 consecutive)

    const float scale = 0.17677669529663687f;  // 1/sqrt(32)

    const float* Qb = Q  + (size_t)bh * LSEQ * DKK + (size_t)q0 * DKK;
    const float* Kb = K  + (size_t)bh * LSEQ * DKK;
    const float* Vb = V  + (size_t)bh * LSEQ * DVV;
    const float* Rb = Rs + (size_t)bh * LSEQ * LSEQ + (size_t)q0 * LSEQ;
    const int*   Mb = Mk + (size_t)bh * LSEQ * LSEQ + (size_t)q0 * LSEQ;
    float*       Sb = out_sc + (size_t)bh * LSEQ * LSEQ + (size_t)q0 * LSEQ;

    // ---- load Q tile (transpose into smem) ----
    {
        const float4* Qg4 = (const float4*)Qb;  // row r has 8 float4
        #pragma unroll
        for (int i = 0; i < 2; i++) {
            int idx = t + i * NTH;             // 0..511
            int r = idx >> 3, f = idx & 7;
            float4 v = Qg4[idx];
            QsT[f*4+0][r] = v.x; QsT[f*4+1][r] = v.y;
            QsT[f*4+2][r] = v.z; QsT[f*4+3][r] = v.w;
        }
    }

    float m[4], l[4], acc[4][2];
    #pragma unroll
    for (int i = 0; i < 4; i++) {
        m[i] = -3.0e38f; l[i] = 0.0f;
        acc[i][0] = 0.0f; acc[i][1] = 0.0f;
    }

    for (int nt = 0; nt < LSEQ / BN; nt++) {
        const int kbase = nt * BN;

        __syncthreads();  // prev iter's Ps/Vs reads done before overwrite
        // ---- load K (transposed) and V tiles ----
        {
            const float4* Kg4 = (const float4*)(Kb + (size_t)kbase * DKK);
            const float4* Vg4 = (const float4*)(Vb + (size_t)kbase * DVV);
            #pragma unroll
            for (int i = 0; i < 2; i++) {
                int idx = t + i * NTH;
                int r = idx >> 3, f = idx & 7;
                float4 kv = Kg4[idx];
                KsT[f*4+0][r] = kv.x; KsT[f*4+1][r] = kv.y;
                KsT[f*4+2][r] = kv.z; KsT[f*4+3][r] = kv.w;
                float4 vv = Vg4[idx];
                *(float4*)&Vs[r][f*4] = vv;
            }
        }
        __syncthreads();  // tiles ready

        // ---- S = Q K^T (4x4 per thread) ----
        float s[4][4];
        #pragma unroll
        for (int i = 0; i < 4; i++)
            #pragma unroll
            for (int j = 0; j < 4; j++) s[i][j] = 0.0f;

        #pragma unroll
        for (int kk = 0; kk < DKK; kk++) {
            float4 q  = *(const float4*)&QsT[kk][r0];
            float4 k4 = *(const float4*)&KsT[kk][c0];
            s[0][0] = fmaf(q.x, k4.x, s[0][0]); s[0][1] = fmaf(q.x, k4.y, s[0][1]);
            s[0][2] = fmaf(q.x, k4.z, s[0][2]); s[0][3] = fmaf(q.x, k4.w, s[0][3]);
            s[1][0] = fmaf(q.y, k4.x, s[1][0]); s[1][1] = fmaf(q.y, k4.y, s[1][1]);
            s[1][2] = fmaf(q.y, k4.z, s[1][2]); s[1][3] = fmaf(q.y, k4.w, s[1][3]);
            s[2][0] = fmaf(q.z, k4.x, s[2][0]); s[2][1] = fmaf(q.z, k4.y, s[2][1]);
            s[2][2] = fmaf(q.z, k4.z, s[2][2]); s[2][3] = fmaf(q.z, k4.w, s[2][3]);
            s[3][0] = fmaf(q.w, k4.x, s[3][0]); s[3][1] = fmaf(q.w, k4.y, s[3][1]);
            s[3][2] = fmaf(q.w, k4.z, s[3][2]); s[3][3] = fmaf(q.w, k4.w, s[3][3]);
        }

        // ---- fuse res_att + mask (int32 bools), stream masked scores ----
        #pragma unroll
        for (int i = 0; i < 4; i++) {
            size_t off = (size_t)(r0 + i) * LSEQ + kbase + c0;
            float4 rv = *(const float4*)(Rb + off);
            int4   mv = *(const int4*)(Mb + off);
            float4 so;
            so.x = mv.x ? -1e9f : fmaf(s[i][0], scale, rv.x);
            so.y = mv.y ? -1e9f : fmaf(s[i][1], scale, rv.y);
            so.z = mv.z ? -1e9f : fmaf(s[i][2], scale, rv.z);
            so.w = mv.w ? -1e9f : fmaf(s[i][3], scale, rv.w);
            *(float4*)(Sb + off) = so;
            s[i][0] = so.x; s[i][1] = so.y; s[i][2] = so.z; s[i][3] = so.w;
        }

        // ---- online softmax update (16-lane row-group reductions) ----
        #pragma unroll
        for (int i = 0; i < 4; i++) {
            float tm = fmaxf(fmaxf(s[i][0], s[i][1]), fmaxf(s[i][2], s[i][3]));
            #pragma unroll
            for (int o = 1; o < 16; o <<= 1)
                tm = fmaxf(tm, __shfl_xor_sync(0xffffffffu, tm, o));
            float mn   = fmaxf(m[i], tm);
            float corr = __expf(m[i] - mn);
            float p0 = __expf(s[i][0] - mn);
            float p1 = __expf(s[i][1] - mn);
            float p2 = __expf(s[i][2] - mn);
            float p3 = __expf(s[i][3] - mn);
            float ps = (p0 + p1) + (p2 + p3);
            #pragma unroll
            for (int o = 1; o < 16; o <<= 1)
                ps += __shfl_xor_sync(0xffffffffu, ps, o);
            l[i] = l[i] * corr + ps;
            m[i] = mn;
            acc[i][0] *= corr; acc[i][1] *= corr;
            float4 pv4 = make_float4(p0, p1, p2, p3);
            *(float4*)&Ps[r0 + i][c0] = pv4;
        }
        __syncthreads();  // Ps ready

        // ---- context += P @ V (4 rows x 2 cols per thread) ----
        #pragma unroll
        for (int n4 = 0; n4 < BN / 4; n4++) {
            const int n = n4 * 4;
            float4 pr0 = *(const float4*)&Ps[r0 + 0][n];
            float4 pr1 = *(const float4*)&Ps[r0 + 1][n];
            float4 pr2 = *(const float4*)&Ps[r0 + 2][n];
            float4 pr3 = *(const float4*)&Ps[r0 + 3][n];
            float2 v0 = *(const float2*)&Vs[n + 0][cc0];
            float2 v1 = *(const float2*)&Vs[n + 1][cc0];
            float2 v2 = *(const float2*)&Vs[n + 2][cc0];
            float2 v3 = *(const float2*)&Vs[n + 3][cc0];

            acc[0][0] = fmaf(pr0.x, v0.x, acc[0][0]); acc[0][1] = fmaf(pr0.x, v0.y, acc[0][1]);
            acc[0][0] = fmaf(pr0.y, v1.x, acc[0][0]); acc[0][1] = fmaf(pr0.y, v1.y, acc[0][1]);
            acc[0][0] = fmaf(pr0.z, v2.x, acc[0][0]); acc[0][1] = fmaf(pr0.z, v2.y, acc[0][1]);
            acc[0][0] = fmaf(pr0.w, v3.x, acc[0][0]); acc[0][1] = fmaf(pr0.w, v3.y, acc[0][1]);

            acc[1][0] = fmaf(pr1.x, v0.x, acc[1][0]); acc[1][1] = fmaf(pr1.x, v0.y, acc[1][1]);
            acc[1][0] = fmaf(pr1.y, v1.x, acc[1][0]); acc[1][1] = fmaf(pr1.y, v1.y, acc[1][1]);
            acc[1][0] = fmaf(pr1.z, v2.x, acc[1][0]); acc[1][1] = fmaf(pr1.z, v2.y, acc[1][1]);
            acc[1][0] = fmaf(pr1.w, v3.x, acc[1][0]); acc[1][1] = fmaf(pr1.w, v3.y, acc[1][1]);

            acc[2][0] = fmaf(pr2.x, v0.x, acc[2][0]); acc[2][1] = fmaf(pr2.x, v0.y, acc[2][1]);
            acc[2][0] = fmaf(pr2.y, v1.x, acc[2][0]); acc[2][1] = fmaf(pr2.y, v1.y, acc[2][1]);
            acc[2][0] = fmaf(pr2.z, v2.x, acc[2][0]); acc[2][1] = fmaf(pr2.z, v2.y, acc[2][1]);
            acc[2][0] = fmaf(pr2.w, v3.x, acc[2][0]); acc[2][1] = fmaf(pr2.w, v3.y, acc[2][1]);

            acc[3][0] = fmaf(pr3.x, v0.x, acc[3][0]); acc[3][1] = fmaf(pr3.x, v0.y, acc[3][1]);
            acc[3][0] = fmaf(pr3.y, v1.x, acc[3][0]); acc[3][1] = fmaf(pr3.y, v1.y, acc[3][1]);
            acc[3][0] = fmaf(pr3.z, v2.x, acc[3][0]); acc[3][1] = fmaf(pr3.z, v2.y, acc[3][1]);
            acc[3][0] = fmaf(pr3.w, v3.x, acc[3][0]); acc[3][1] = fmaf(pr3.w, v3.y, acc[3][1]);
        }
    }

    // ---- epilogue: context = acc / l ----
    #pragma unroll
    for (int i = 0; i < 4; i++) {
        float inv = 1.0f / l[i];
        float2 o;
        o.x = acc[i][0] * inv;
        o.y = acc[i][1] * inv;
        *(float2*)(out_ctx + (size_t)(bh * LSEQ + q0 + r0 + i) * DVV + cc0) = o;
    }
}

extern "C" void kernel_launch(void* const* d_in, const int* in_sizes, int n_in,
                              void* d_out, int out_size)
{
    (void)in_sizes; (void)n_in; (void)out_size;
    const float* Q  = (const float*)d_in[0];
    const float* K  = (const float*)d_in[1];
    const float* V  = (const float*)d_in[2];
    const int*   Mk = (const int*)d_in[3];
    const float* Rs = (const float*)d_in[4];

    float* out     = (float*)d_out;
    float* out_ctx = out;                                              // [B,H,L,DV]
    float* out_sc  = out + (size_t)BATCH * HEADS * LSEQ * DVV;         // [B,H,L,L]

    dim3 grid(LSEQ / BM, BHN);
    attn_fused_kernel<<<grid, NTH>>>(Q, K, V, Mk, Rs, out_ctx, out_sc);
}

// round 5
// speedup vs baseline: 1.1389x; 1.1389x over previous
#include <cuda_runtime.h>
#include <cstdint>

#define BATCH 4
#define HEADS 8
#define LSEQ  2048
#define DKK   32
#define DVV   32
#define BM    128
#define BN    64
#define NTH   256
#define KP    36   // K smem pitch (floats, 32-wide rows): frag banks (4g+tig) -> conflict-free
#define VP    40   // V smem pitch (32-wide rows): frag banks (8tig+g) -> conflict-free
#define PP    68   // P/S smem pitch (64-wide rows!): >=64, banks (4g+...) -> conflict-free

__device__ __forceinline__ uint32_t f2tf32(float x) {
    uint32_t u; asm("cvt.rna.tf32.f32 %0, %1;" : "=r"(u) : "f"(x)); return u;
}

__device__ __forceinline__ void split1(float v, float& h, float& l) {
    uint32_t hu = f2tf32(v);
    h = __uint_as_float(hu);
    l = __uint_as_float(f2tf32(v - h));
}

__device__ __forceinline__ void split4(float4 v, float4& h, float4& l) {
    split1(v.x, h.x, l.x); split1(v.y, h.y, l.y);
    split1(v.z, h.z, l.z); split1(v.w, h.w, l.w);
}

__device__ __forceinline__ void mma_tf32(float* d, const uint32_t* a, const uint32_t* b) {
    asm volatile("mma.sync.aligned.m16n8k8.row.col.f32.tf32.tf32.f32 "
        "{%0,%1,%2,%3}, {%4,%5,%6,%7}, {%8,%9}, {%0,%1,%2,%3};"
        : "+f"(d[0]), "+f"(d[1]), "+f"(d[2]), "+f"(d[3])
        : "r"(a[0]), "r"(a[1]), "r"(a[2]), "r"(a[3]), "r"(b[0]), "r"(b[1]));
}

__global__ void __launch_bounds__(NTH, 2)
attn_tc_kernel(const float* __restrict__ Q, const float* __restrict__ K,
               const float* __restrict__ V, const int* __restrict__ Mk,
               const float* __restrict__ Rs, float* __restrict__ out_ctx,
               float* __restrict__ out_sc)
{
    extern __shared__ float sm[];
    float* KsH = sm;                  // 64*KP
    float* KsL = KsH + 64*KP;
    float* VsH = KsL + 64*KP;         // 64*VP
    float* VsL = VsH + 64*VP;
    float* PsH = VsL + 64*VP;         // BM*PP (also S scratch)
    float* PsL = PsH + BM*PP;
    float* m_s = PsL + BM*PP;         // BM
    float* l_s = m_s + BM;            // BM
    float* c_s = l_s + BM;            // BM

    const int t    = threadIdx.x;
    const int w    = t >> 5;
    const int lane = t & 31;
    const int g    = lane >> 2;   // 0..7
    const int tig  = lane & 3;    // 0..3
    const int half = lane >> 4;   // 0/1
    const int c4   = lane & 15;   // 0..15
    const int bh   = blockIdx.y;
    const int q0   = blockIdx.x * BM;

    const float scale = 0.17677669529663687f;  // 1/sqrt(32)

    const float* Kb    = K  + (size_t)bh * LSEQ * DKK;
    const float* Vb    = V  + (size_t)bh * LSEQ * DVV;
    const float* Rball = Rs + (size_t)bh * LSEQ * LSEQ;
    const int*   Mball = Mk + (size_t)bh * LSEQ * LSEQ;
    float*       Sball = out_sc + (size_t)bh * LSEQ * LSEQ;

    if (t < BM) { m_s[t] = -3.0e38f; l_s[t] = 0.0f; }

    // ---- Q fragments (tf32 hi/lo), held in registers for the whole kernel ----
    uint32_t qH[4][4], qL[4][4];
    {
        const float* Qw = Q + ((size_t)bh * LSEQ + q0 + 16*w) * DKK;
        #pragma unroll
        for (int ks = 0; ks < 4; ks++) {
            float v0 = Qw[(size_t)g*DKK       + 8*ks + tig];
            float v1 = Qw[(size_t)(g+8)*DKK   + 8*ks + tig];
            float v2 = Qw[(size_t)g*DKK       + 8*ks + tig + 4];
            float v3 = Qw[(size_t)(g+8)*DKK   + 8*ks + tig + 4];
            float h, l;
            split1(v0, h, l); qH[ks][0] = __float_as_uint(h); qL[ks][0] = __float_as_uint(l);
            split1(v1, h, l); qH[ks][1] = __float_as_uint(h); qL[ks][1] = __float_as_uint(l);
            split1(v2, h, l); qH[ks][2] = __float_as_uint(h); qL[ks][2] = __float_as_uint(l);
            split1(v3, h, l); qH[ks][3] = __float_as_uint(h); qL[ks][3] = __float_as_uint(l);
        }
    }

    float ctx[4][4];
    #pragma unroll
    for (int i = 0; i < 4; i++)
        #pragma unroll
        for (int j = 0; j < 4; j++) ctx[i][j] = 0.0f;

    for (int kt = 0; kt < LSEQ / BN; kt++) {
        const int kbase = kt * BN;

        __syncthreads();  // protect Ks/Vs from prior reads

        // ---- stage K,V tiles as tf32 hi/lo ----
        {
            const float4* Kg4 = (const float4*)(Kb + (size_t)kbase * DKK);
            const float4* Vg4 = (const float4*)(Vb + (size_t)kbase * DVV);
            #pragma unroll
            for (int i = 0; i < 2; i++) {
                int id = t + i * NTH;        // 0..511 (64 rows x 8 float4)
                int r = id >> 3, c = (id & 7) * 4;
                float4 kv = Kg4[id], kh, kl;
                split4(kv, kh, kl);
                *(float4*)(KsH + r*KP + c) = kh;
                *(float4*)(KsL + r*KP + c) = kl;
                float4 vv = Vg4[id], vh, vl;
                split4(vv, vh, vl);
                *(float4*)(VsH + r*VP + c) = vh;
                *(float4*)(VsL + r*VP + c) = vl;
            }
        }
        __syncthreads();

        // ---- S = Q K^T  (x3 tf32 split), D-layout regs ----
        float sD[8][4];
        #pragma unroll
        for (int i = 0; i < 8; i++)
            #pragma unroll
            for (int j = 0; j < 4; j++) sD[i][j] = 0.0f;

        #pragma unroll
        for (int ks = 0; ks < 4; ks++) {
            #pragma unroll
            for (int n8 = 0; n8 < 8; n8++) {
                const float* kh = KsH + (8*n8 + g)*KP + 8*ks + tig;
                const float* kl = KsL + (8*n8 + g)*KP + 8*ks + tig;
                uint32_t bH[2] = { *(const uint32_t*)kh, *(const uint32_t*)(kh + 4) };
                uint32_t bL[2] = { *(const uint32_t*)kl, *(const uint32_t*)(kl + 4) };
                mma_tf32(sD[n8], qH[ks], bH);
                mma_tf32(sD[n8], qL[ks], bH);
                mma_tf32(sD[n8], qH[ks], bL);
            }
        }

        // ---- dump S (D-layout) to warp-private smem scratch ----
        #pragma unroll
        for (int n8 = 0; n8 < 8; n8++) {
            *(float2*)(PsH + (16*w + g    )*PP + 8*n8 + 2*tig) = make_float2(sD[n8][0], sD[n8][1]);
            *(float2*)(PsH + (16*w + g + 8)*PP + 8*n8 + 2*tig) = make_float2(sD[n8][2], sD[n8][3]);
        }
        __syncwarp();

        // ---- coalesced epilogue: res+mask+scores IO, online softmax, P hi/lo ----
        #pragma unroll
        for (int pp = 0; pp < 8; pp++) {
            int R = 16*w + 2*pp + half;
            float4 s4 = *(float4*)(PsH + R*PP + c4*4);
            size_t off = (size_t)(q0 + R) * LSEQ + kbase + c4*4;
            float4 rv = *(const float4*)(Rball + off);
            int4   mv = *(const int4*)(Mball + off);
            float4 so;
            so.x = mv.x ? -1e9f : fmaf(s4.x, scale, rv.x);
            so.y = mv.y ? -1e9f : fmaf(s4.y, scale, rv.y);
            so.z = mv.z ? -1e9f : fmaf(s4.z, scale, rv.z);
            so.w = mv.w ? -1e9f : fmaf(s4.w, scale, rv.w);
            *(float4*)(Sball + off) = so;

            float rmax = fmaxf(fmaxf(so.x, so.y), fmaxf(so.z, so.w));
            #pragma unroll
            for (int o = 1; o < 16; o <<= 1)
                rmax = fmaxf(rmax, __shfl_xor_sync(0xffffffffu, rmax, o));
            float mo = m_s[R];
            float mn = fmaxf(mo, rmax);
            float corr = __expf(mo - mn);
            float p0 = __expf(so.x - mn), p1 = __expf(so.y - mn);
            float p2 = __expf(so.z - mn), p3 = __expf(so.w - mn);
            float rsum = (p0 + p1) + (p2 + p3);
            #pragma unroll
            for (int o = 1; o < 16; o <<= 1)
                rsum += __shfl_xor_sync(0xffffffffu, rsum, o);
            if (c4 == 0) { m_s[R] = mn; l_s[R] = l_s[R]*corr + rsum; c_s[R] = corr; }

            float4 h4, l4;
            split1(p0, h4.x, l4.x); split1(p1, h4.y, l4.y);
            split1(p2, h4.z, l4.z); split1(p3, h4.w, l4.w);
            *(float4*)(PsH + R*PP + c4*4) = h4;
            *(float4*)(PsL + R*PP + c4*4) = l4;
        }
        __syncwarp();

        // ---- rescale ctx, then ctx += P V (x3 tf32 split) ----
        {
            float cA = c_s[16*w + g], cB = c_s[16*w + g + 8];
            #pragma unroll
            for (int n8 = 0; n8 < 4; n8++) {
                ctx[n8][0] *= cA; ctx[n8][1] *= cA;
                ctx[n8][2] *= cB; ctx[n8][3] *= cB;
            }
        }
        #pragma unroll
        for (int ks = 0; ks < 8; ks++) {
            const float* pa = PsH + (16*w + g    )*PP + 8*ks + tig;
            const float* pb = PsH + (16*w + g + 8)*PP + 8*ks + tig;
            const float* la = PsL + (16*w + g    )*PP + 8*ks + tig;
            const float* lb = PsL + (16*w + g + 8)*PP + 8*ks + tig;
            uint32_t aH[4] = { *(const uint32_t*)pa, *(const uint32_t*)pb,
                               *(const uint32_t*)(pa + 4), *(const uint32_t*)(pb + 4) };
            uint32_t aL[4] = { *(const uint32_t*)la, *(const uint32_t*)lb,
                               *(const uint32_t*)(la + 4), *(const uint32_t*)(lb + 4) };
            #pragma unroll
            for (int n8 = 0; n8 < 4; n8++) {
                const float* vh0 = VsH + (8*ks + tig    )*VP + 8*n8 + g;
                const float* vh1 = VsH + (8*ks + tig + 4)*VP + 8*n8 + g;
                const float* vl0 = VsL + (8*ks + tig    )*VP + 8*n8 + g;
                const float* vl1 = VsL + (8*ks + tig + 4)*VP + 8*n8 + g;
                uint32_t bH[2] = { *(const uint32_t*)vh0, *(const uint32_t*)vh1 };
                uint32_t bL[2] = { *(const uint32_t*)vl0, *(const uint32_t*)vl1 };
                mma_tf32(ctx[n8], aH, bH);
                mma_tf32(ctx[n8], aL, bH);
                mma_tf32(ctx[n8], aH, bL);
            }
        }
    }

    // ---- final: ctx / l ----
    __syncwarp();
    {
        float invA = 1.0f / l_s[16*w + g];
        float invB = 1.0f / l_s[16*w + g + 8];
        float* o0 = out_ctx + ((size_t)bh * LSEQ + q0 + 16*w + g    ) * DVV;
        float* o1 = out_ctx + ((size_t)bh * LSEQ + q0 + 16*w + g + 8) * DVV;
        #pragma unroll
        for (int n8 = 0; n8 < 4; n8++) {
            *(float2*)(o0 + 8*n8 + 2*tig) = make_float2(ctx[n8][0]*invA, ctx[n8][1]*invA);
            *(float2*)(o1 + 8*n8 + 2*tig) = make_float2(ctx[n8][2]*invB, ctx[n8][3]*invB);
        }
    }
}

extern "C" void kernel_launch(void* const* d_in, const int* in_sizes, int n_in,
                              void* d_out, int out_size)
{
    (void)in_sizes; (void)n_in; (void)out_size;
    const float* Q  = (const float*)d_in[0];
    const float* K  = (const float*)d_in[1];
    const float* V  = (const float*)d_in[2];
    const int*   Mk = (const int*)d_in[3];
    const float* Rs = (const float*)d_in[4];

    float* out     = (float*)d_out;
    float* out_ctx = out;                                        // [B,H,L,DV]
    float* out_sc  = out + (size_t)BATCH * HEADS * LSEQ * DVV;   // [B,H,L,L]

    const size_t SMEM_BYTES = (size_t)(2*64*KP + 2*64*VP + 2*BM*PP + 3*BM) * sizeof(float);
    cudaFuncSetAttribute((const void*)attn_tc_kernel,
                         cudaFuncAttributeMaxDynamicSharedMemorySize, (int)SMEM_BYTES);

    dim3 grid(LSEQ / BM, BATCH * HEADS);
    attn_tc_kernel<<<grid, NTH, SMEM_BYTES>>>(Q, K, V, Mk, Rs, out_ctx, out_sc);
}

// round 8
// speedup vs baseline: 1.1862x; 1.0416x over previous
#include <cuda_runtime.h>
#include <cstdint>

#define BATCH 4
#define HEADS 8
#define LSEQ  2048
#define DKK   32
#define DVV   32
#define BM    128
#define BN    64
#define NTH   256
#define KP    36   // K smem pitch (32-wide rows): frag banks conflict-free
#define VP    40   // V smem pitch (32-wide rows): frag banks conflict-free
#define PP    68   // P/S smem pitch (64-wide rows): conflict-free frag reads
#define RP    64   // res_att smem pitch

__device__ __forceinline__ uint32_t f2tf32(float x) {
    uint32_t u; asm("cvt.rna.tf32.f32 %0, %1;" : "=r"(u) : "f"(x)); return u;
}

__device__ __forceinline__ void split1(float v, float& h, float& l) {
    h = __uint_as_float(f2tf32(v));
    l = __uint_as_float(f2tf32(v - h));
}

__device__ __forceinline__ void split4(float4 v, float4& h, float4& l) {
    split1(v.x, h.x, l.x); split1(v.y, h.y, l.y);
    split1(v.z, h.z, l.z); split1(v.w, h.w, l.w);
}

__device__ __forceinline__ void mma_tf32(float* d, const uint32_t* a, const uint32_t* b) {
    asm volatile("mma.sync.aligned.m16n8k8.row.col.f32.tf32.tf32.f32 "
        "{%0,%1,%2,%3}, {%4,%5,%6,%7}, {%8,%9}, {%0,%1,%2,%3};"
        : "+f"(d[0]), "+f"(d[1]), "+f"(d[2]), "+f"(d[3])
        : "r"(a[0]), "r"(a[1]), "r"(a[2]), "r"(a[3]), "r"(b[0]), "r"(b[1]));
}

#define CP_ASYNC16(dst_u32, src_ptr) \
    asm volatile("cp.async.cg.shared.global [%0], [%1], 16;" :: "r"(dst_u32), "l"(src_ptr))

__global__ void __launch_bounds__(NTH, 2)
attn_tc_kernel(const float* __restrict__ Q, const float* __restrict__ K,
               const float* __restrict__ V, const int* __restrict__ Mk,
               const float* __restrict__ Rs, float* __restrict__ out_ctx,
               float* __restrict__ out_sc)
{
    extern __shared__ float sm[];
    float* KsH = sm;                  // 64*KP
    float* KsL = KsH + 64*KP;
    float* VsH = KsL + 64*KP;         // 64*VP
    float* VsL = VsH + 64*VP;
    float* Ps  = VsL + 64*VP;         // BM*PP : S scratch, then P (fp32)
    float* Rsm = Ps  + BM*PP;         // BM*RP : res_att prefetch buffer
    float* m_s = Rsm + BM*RP;         // BM
    float* l_s = m_s + BM;            // BM
    float* c_s = l_s + BM;            // BM

    const int t    = threadIdx.x;
    const int w    = t >> 5;
    const int lane = t & 31;
    const int g    = lane >> 2;   // 0..7
    const int tig  = lane & 3;    // 0..3
    const int half = lane >> 4;   // 0/1
    const int c4   = lane & 15;   // 0..15
    const int bh   = blockIdx.y;
    const int q0   = blockIdx.x * BM;

    const float scale = 0.17677669529663687f;  // 1/sqrt(32)

    const float* Kb    = K  + (size_t)bh * LSEQ * DKK;
    const float* Vb    = V  + (size_t)bh * LSEQ * DVV;
    const float* Rball = Rs + (size_t)bh * LSEQ * LSEQ;
    const int*   Mball = Mk + (size_t)bh * LSEQ * LSEQ;
    float*       Sball = out_sc + (size_t)bh * LSEQ * LSEQ;

    const uint32_t Rsm_u32 = (uint32_t)__cvta_generic_to_shared(Rsm);

    if (t < BM) { m_s[t] = -3.0e38f; l_s[t] = 0.0f; }

    // ---- Q fragments (tf32 hi/lo), registers for the whole kernel ----
    uint32_t qH[4][4], qL[4][4];
    {
        const float* Qw = Q + ((size_t)bh * LSEQ + q0 + 16*w) * DKK;
        #pragma unroll
        for (int ks = 0; ks < 4; ks++) {
            float v0 = Qw[(size_t)g*DKK     + 8*ks + tig];
            float v1 = Qw[(size_t)(g+8)*DKK + 8*ks + tig];
            float v2 = Qw[(size_t)g*DKK     + 8*ks + tig + 4];
            float v3 = Qw[(size_t)(g+8)*DKK + 8*ks + tig + 4];
            float h, l;
            split1(v0, h, l); qH[ks][0] = __float_as_uint(h); qL[ks][0] = __float_as_uint(l);
            split1(v1, h, l); qH[ks][1] = __float_as_uint(h); qL[ks][1] = __float_as_uint(l);
            split1(v2, h, l); qH[ks][2] = __float_as_uint(h); qL[ks][2] = __float_as_uint(l);
            split1(v3, h, l); qH[ks][3] = __float_as_uint(h); qL[ks][3] = __float_as_uint(l);
        }
    }

    float ctx[4][4];
    #pragma unroll
    for (int i = 0; i < 4; i++)
        #pragma unroll
        for (int j = 0; j < 4; j++) ctx[i][j] = 0.0f;

    for (int kt = 0; kt < LSEQ / BN; kt++) {
        const int kbase = kt * BN;

        __syncthreads();  // prev-tile K/V frag reads complete; also first-tile m_s/l_s init

        // ---- issue cp.async prefetch of this tile's res_att (warp-local rows) ----
        {
            #pragma unroll
            for (int j = 0; j < 8; j++) {
                int idx = j * 32 + lane;          // 0..255
                int rl  = idx >> 4;               // 0..15 (row within warp's 16)
                int cf  = (idx & 15) * 4;         // float4 col
                const float* src = Rball + (size_t)(q0 + 16*w + rl) * LSEQ + kbase + cf;
                uint32_t dst = Rsm_u32 + (uint32_t)(((16*w + rl) * RP + cf) * 4);
                CP_ASYNC16(dst, src);
            }
            asm volatile("cp.async.commit_group;");
        }

        // ---- stage K,V tiles as tf32 hi/lo ----
        {
            const float4* Kg4 = (const float4*)(Kb + (size_t)kbase * DKK);
            const float4* Vg4 = (const float4*)(Vb + (size_t)kbase * DVV);
            #pragma unroll
            for (int i = 0; i < 2; i++) {
                int id = t + i * NTH;        // 0..511 (64 rows x 8 float4)
                int r = id >> 3, c = (id & 7) * 4;
                float4 kv = Kg4[id], kh, kl;
                split4(kv, kh, kl);
                *(float4*)(KsH + r*KP + c) = kh;
                *(float4*)(KsL + r*KP + c) = kl;
                float4 vv = Vg4[id], vh, vl;
                split4(vv, vh, vl);
                *(float4*)(VsH + r*VP + c) = vh;
                *(float4*)(VsL + r*VP + c) = vl;
            }
        }
        __syncthreads();

        // ---- S = Q K^T  (x3 tf32 split), D-layout regs ----
        float sD[8][4];
        #pragma unroll
        for (int i = 0; i < 8; i++)
            #pragma unroll
            for (int j = 0; j < 4; j++) sD[i][j] = 0.0f;

        #pragma unroll
        for (int ks = 0; ks < 4; ks++) {
            #pragma unroll
            for (int n8 = 0; n8 < 8; n8++) {
                const float* kh = KsH + (8*n8 + g)*KP + 8*ks + tig;
                const float* kl = KsL + (8*n8 + g)*KP + 8*ks + tig;
                uint32_t bH[2] = { *(const uint32_t*)kh, *(const uint32_t*)(kh + 4) };
                uint32_t bL[2] = { *(const uint32_t*)kl, *(const uint32_t*)(kl + 4) };
                mma_tf32(sD[n8], qH[ks], bH);
                mma_tf32(sD[n8], qL[ks], bH);
                mma_tf32(sD[n8], qH[ks], bL);
            }
        }

        // ---- dump S (D-layout) to warp-private smem scratch ----
        #pragma unroll
        for (int n8 = 0; n8 < 8; n8++) {
            *(float2*)(Ps + (16*w + g    )*PP + 8*n8 + 2*tig) = make_float2(sD[n8][0], sD[n8][1]);
            *(float2*)(Ps + (16*w + g + 8)*PP + 8*n8 + 2*tig) = make_float2(sD[n8][2], sD[n8][3]);
        }
        asm volatile("cp.async.wait_group 0;");
        __syncwarp();   // S scratch + warp's res_att rows visible

        // ---- epilogue: mask (2-deep pipelined LDG) + res (LDS) + scores STG + softmax ----
        {
            int4 mv0 = *(const int4*)(Mball + (size_t)(q0 + 16*w + half) * LSEQ + kbase + c4*4);
            int4 mv1 = *(const int4*)(Mball + (size_t)(q0 + 16*w + 2 + half) * LSEQ + kbase + c4*4);
            #pragma unroll
            for (int pp = 0; pp < 8; pp++) {
                int R = 16*w + 2*pp + half;
                int4 mv = mv0;
                mv0 = mv1;
                if (pp < 6)
                    mv1 = *(const int4*)(Mball + (size_t)(q0 + 16*w + 2*(pp+2) + half) * LSEQ + kbase + c4*4);

                float4 s4 = *(float4*)(Ps + R*PP + c4*4);
                float4 rv = *(float4*)(Rsm + R*RP + c4*4);
                size_t off = (size_t)(q0 + R) * LSEQ + kbase + c4*4;
                float4 so;
                so.x = mv.x ? -1e9f : fmaf(s4.x, scale, rv.x);
                so.y = mv.y ? -1e9f : fmaf(s4.y, scale, rv.y);
                so.z = mv.z ? -1e9f : fmaf(s4.z, scale, rv.z);
                so.w = mv.w ? -1e9f : fmaf(s4.w, scale, rv.w);
                *(float4*)(Sball + off) = so;

                float rmax = fmaxf(fmaxf(so.x, so.y), fmaxf(so.z, so.w));
                #pragma unroll
                for (int o = 1; o < 16; o <<= 1)
                    rmax = fmaxf(rmax, __shfl_xor_sync(0xffffffffu, rmax, o));
                float mo = m_s[R];
                float mn = fmaxf(mo, rmax);
                float corr = __expf(mo - mn);
                float p0 = __expf(so.x - mn), p1 = __expf(so.y - mn);
                float p2 = __expf(so.z - mn), p3 = __expf(so.w - mn);
                float rsum = (p0 + p1) + (p2 + p3);
                #pragma unroll
                for (int o = 1; o < 16; o <<= 1)
                    rsum += __shfl_xor_sync(0xffffffffu, rsum, o);
                if (c4 == 0) { m_s[R] = mn; l_s[R] = l_s[R]*corr + rsum; c_s[R] = corr; }

                *(float4*)(Ps + R*PP + c4*4) = make_float4(p0, p1, p2, p3);
            }
        }
        __syncwarp();

        // ---- rescale ctx, then ctx += P V (x3 tf32 split; P split at frag load) ----
        {
            float cA = c_s[16*w + g], cB = c_s[16*w + g + 8];
            #pragma unroll
            for (int n8 = 0; n8 < 4; n8++) {
                ctx[n8][0] *= cA; ctx[n8][1] *= cA;
                ctx[n8][2] *= cB; ctx[n8][3] *= cB;
            }
        }
        #pragma unroll
        for (int ks = 0; ks < 8; ks++) {
            float pa  = *(Ps + (16*w + g    )*PP + 8*ks + tig);
            float pb  = *(Ps + (16*w + g + 8)*PP + 8*ks + tig);
            float pa4 = *(Ps + (16*w + g    )*PP + 8*ks + tig + 4);
            float pb4 = *(Ps + (16*w + g + 8)*PP + 8*ks + tig + 4);
            uint32_t aH[4], aL[4];
            float h, l;
            split1(pa,  h, l); aH[0] = __float_as_uint(h); aL[0] = __float_as_uint(l);
            split1(pb,  h, l); aH[1] = __float_as_uint(h); aL[1] = __float_as_uint(l);
            split1(pa4, h, l); aH[2] = __float_as_uint(h); aL[2] = __float_as_uint(l);
            split1(pb4, h, l); aH[3] = __float_as_uint(h); aL[3] = __float_as_uint(l);
            #pragma unroll
            for (int n8 = 0; n8 < 4; n8++) {
                const float* vh0 = VsH + (8*ks + tig    )*VP + 8*n8 + g;
                const float* vh1 = VsH + (8*ks + tig + 4)*VP + 8*n8 + g;
                const float* vl0 = VsL + (8*ks + tig    )*VP + 8*n8 + g;
                const float* vl1 = VsL + (8*ks + tig + 4)*VP + 8*n8 + g;
                uint32_t bH[2] = { *(const uint32_t*)vh0, *(const uint32_t*)vh1 };
                uint32_t bL[2] = { *(const uint32_t*)vl0, *(const uint32_t*)vl1 };
                mma_tf32(ctx[n8], aH, bH);
                mma_tf32(ctx[n8], aL, bH);
                mma_tf32(ctx[n8], aH, bL);
            }
        }
    }

    // ---- final: ctx / l ----
    __syncwarp();
    {
        float invA = 1.0f / l_s[16*w + g];
        float invB = 1.0f / l_s[16*w + g + 8];
        float* o0 = out_ctx + ((size_t)bh * LSEQ + q0 + 16*w + g    ) * DVV;
        float* o1 = out_ctx + ((size_t)bh * LSEQ + q0 + 16*w + g + 8) * DVV;
        #pragma unroll
        for (int n8 = 0; n8 < 4; n8++) {
            *(float2*)(o0 + 8*n8 + 2*tig) = make_float2(ctx[n8][0]*invA, ctx[n8][1]*invA);
            *(float2*)(o1 + 8*n8 + 2*tig) = make_float2(ctx[n8][2]*invB, ctx[n8][3]*invB);
        }
    }
}

extern "C" void kernel_launch(void* const* d_in, const int* in_sizes, int n_in,
                              void* d_out, int out_size)
{
    (void)in_sizes; (void)n_in; (void)out_size;
    const float* Q  = (const float*)d_in[0];
    const float* K  = (const float*)d_in[1];
    const float* V  = (const float*)d_in[2];
    const int*   Mk = (const int*)d_in[3];
    const float* Rs = (const float*)d_in[4];

    float* out     = (float*)d_out;
    float* out_ctx = out;                                        // [B,H,L,DV]
    float* out_sc  = out + (size_t)BATCH * HEADS * LSEQ * DVV;   // [B,H,L,L]

    const size_t SMEM_BYTES = (size_t)(2*64*KP + 2*64*VP + BM*PP + BM*RP + 3*BM) * sizeof(float);
    cudaFuncSetAttribute((const void*)attn_tc_kernel,
                         cudaFuncAttributeMaxDynamicSharedMemorySize, (int)SMEM_BYTES);

    dim3 grid(LSEQ / BM, BATCH * HEADS);
    attn_tc_kernel<<<grid, NTH, SMEM_BYTES>>>(Q, K, V, Mk, Rs, out_ctx, out_sc);
}

// round 9
// speedup vs baseline: 1.3152x; 1.1087x over previous
#include <cuda_runtime.h>
#include <cstdint>

#define BATCH 4
#define HEADS 8
#define LSEQ  2048
#define DKK   32
#define DVV   32
#define BM    128
#define BN    64
#define NTH   256
#define KP    36   // K smem pitch (32-wide rows): frag banks conflict-free
#define VP    40   // V smem pitch (32-wide rows): frag banks conflict-free
#define PP    68   // P smem pitch (64-wide rows): conflict-free frag reads

__device__ __forceinline__ uint32_t f2tf32(float x) {
    uint32_t u; asm("cvt.rna.tf32.f32 %0, %1;" : "=r"(u) : "f"(x)); return u;
}

__device__ __forceinline__ void split1(float v, float& h, float& l) {
    h = __uint_as_float(f2tf32(v));
    l = __uint_as_float(f2tf32(v - h));
}

__device__ __forceinline__ void split4(float4 v, float4& h, float4& l) {
    split1(v.x, h.x, l.x); split1(v.y, h.y, l.y);
    split1(v.z, h.z, l.z); split1(v.w, h.w, l.w);
}

__device__ __forceinline__ void mma_tf32(float* d, const uint32_t* a, const uint32_t* b) {
    asm volatile("mma.sync.aligned.m16n8k8.row.col.f32.tf32.tf32.f32 "
        "{%0,%1,%2,%3}, {%4,%5,%6,%7}, {%8,%9}, {%0,%1,%2,%3};"
        : "+f"(d[0]), "+f"(d[1]), "+f"(d[2]), "+f"(d[3])
        : "r"(a[0]), "r"(a[1]), "r"(a[2]), "r"(a[3]), "r"(b[0]), "r"(b[1]));
}

__global__ void __launch_bounds__(NTH, 2)
attn_tc_kernel(const float* __restrict__ Q, const float* __restrict__ K,
               const float* __restrict__ V, const int* __restrict__ Mk,
               const float* __restrict__ Rs, float* __restrict__ out_ctx,
               float* __restrict__ out_sc)
{
    extern __shared__ float sm[];
    float* KsH = sm;                  // 64*KP
    float* KsL = KsH + 64*KP;
    float* VsH = KsL + 64*KP;         // 64*VP
    float* VsL = VsH + 64*VP;
    float* Ps  = VsL + 64*VP;         // BM*PP : P (fp32), warp-private rows

    const int t    = threadIdx.x;
    const int w    = t >> 5;
    const int lane = t & 31;
    const int g    = lane >> 2;   // 0..7
    const int tig  = lane & 3;    // 0..3
    const int bh   = blockIdx.y;
    const int q0   = blockIdx.x * BM;

    const float scale = 0.17677669529663687f;  // 1/sqrt(32)

    const float* Kb    = K  + (size_t)bh * LSEQ * DKK;
    const float* Vb    = V  + (size_t)bh * LSEQ * DVV;
    const float* Rball = Rs + (size_t)bh * LSEQ * LSEQ;
    const int*   Mball = Mk + (size_t)bh * LSEQ * LSEQ;
    float*       Sball = out_sc + (size_t)bh * LSEQ * LSEQ;

    // ---- Q in fp32 regs, A-fragment pattern (split to tf32 per-tile) ----
    float qf[4][4];
    {
        const float* Qw = Q + ((size_t)bh * LSEQ + q0 + 16*w) * DKK;
        #pragma unroll
        for (int ks = 0; ks < 4; ks++) {
            qf[ks][0] = Qw[(size_t)g*DKK     + 8*ks + tig];
            qf[ks][1] = Qw[(size_t)(g+8)*DKK + 8*ks + tig];
            qf[ks][2] = Qw[(size_t)g*DKK     + 8*ks + tig + 4];
            qf[ks][3] = Qw[(size_t)(g+8)*DKK + 8*ks + tig + 4];
        }
    }

    float ctx[4][4];
    #pragma unroll
    for (int i = 0; i < 4; i++)
        #pragma unroll
        for (int j = 0; j < 4; j++) ctx[i][j] = 0.0f;

    // per-row softmax state (rows g and g+8 of this warp's 16), registers only
    float mA = -3.0e38f, mB = -3.0e38f, lA = 0.0f, lB = 0.0f;

    for (int kt = 0; kt < LSEQ / BN; kt++) {
        const int kbase = kt * BN;

        __syncthreads();  // prev-tile K/V frag reads complete

        // ---- stage K,V tiles as tf32 hi/lo ----
        {
            const float4* Kg4 = (const float4*)(Kb + (size_t)kbase * DKK);
            const float4* Vg4 = (const float4*)(Vb + (size_t)kbase * DVV);
            #pragma unroll
            for (int i = 0; i < 2; i++) {
                int id = t + i * NTH;        // 0..511 (64 rows x 8 float4)
                int r = id >> 3, c = (id & 7) * 4;
                float4 kv = Kg4[id], kh, kl;
                split4(kv, kh, kl);
                *(float4*)(KsH + r*KP + c) = kh;
                *(float4*)(KsL + r*KP + c) = kl;
                float4 vv = Vg4[id], vh, vl;
                split4(vv, vh, vl);
                *(float4*)(VsH + r*VP + c) = vh;
                *(float4*)(VsL + r*VP + c) = vl;
            }
        }
        __syncthreads();

        // ---- S = Q K^T (x3 tf32 split), D-layout regs ----
        float sD[8][4];
        #pragma unroll
        for (int i = 0; i < 8; i++)
            #pragma unroll
            for (int j = 0; j < 4; j++) sD[i][j] = 0.0f;

        #pragma unroll
        for (int ks = 0; ks < 4; ks++) {
            uint32_t qH[4], qL[4];
            #pragma unroll
            for (int j = 0; j < 4; j++) {
                float h, l;
                split1(qf[ks][j], h, l);
                qH[j] = __float_as_uint(h); qL[j] = __float_as_uint(l);
            }
            #pragma unroll
            for (int n8 = 0; n8 < 8; n8++) {
                const float* kh = KsH + (8*n8 + g)*KP + 8*ks + tig;
                const float* kl = KsL + (8*n8 + g)*KP + 8*ks + tig;
                uint32_t bH[2] = { *(const uint32_t*)kh, *(const uint32_t*)(kh + 4) };
                uint32_t bL[2] = { *(const uint32_t*)kl, *(const uint32_t*)(kl + 4) };
                mma_tf32(sD[n8], qH, bH);
                mma_tf32(sD[n8], qL, bH);
                mma_tf32(sD[n8], qH, bL);
            }
        }

        // ---- epilogue: res+mask (D-pattern, streaming), scores STG, reg softmax ----
        const size_t rowA = (size_t)(q0 + 16*w + g) * LSEQ + kbase + 2*tig;
        const size_t rowB = rowA + (size_t)8 * LSEQ;

        {
            float2 rA[8], rB[8];
            int2   mkA[8], mkB[8];
            #pragma unroll
            for (int n8 = 0; n8 < 8; n8++) {
                rA[n8]  = __ldcs((const float2*)(Rball + rowA + 8*n8));
                rB[n8]  = __ldcs((const float2*)(Rball + rowB + 8*n8));
                mkA[n8] = __ldcs((const int2*)(Mball + rowA + 8*n8));
                mkB[n8] = __ldcs((const int2*)(Mball + rowB + 8*n8));
            }
            #pragma unroll
            for (int n8 = 0; n8 < 8; n8++) {
                float2 soA, soB;
                soA.x = mkA[n8].x ? -1e9f : fmaf(sD[n8][0], scale, rA[n8].x);
                soA.y = mkA[n8].y ? -1e9f : fmaf(sD[n8][1], scale, rA[n8].y);
                soB.x = mkB[n8].x ? -1e9f : fmaf(sD[n8][2], scale, rB[n8].x);
                soB.y = mkB[n8].y ? -1e9f : fmaf(sD[n8][3], scale, rB[n8].y);
                __stcs((float2*)(Sball + rowA + 8*n8), soA);
                __stcs((float2*)(Sball + rowB + 8*n8), soB);
                sD[n8][0] = soA.x; sD[n8][1] = soA.y;
                sD[n8][2] = soB.x; sD[n8][3] = soB.y;
            }
        }

        // row max over quad (each row's 64 cols live in 4 lanes)
        float mxA = sD[0][0], mxB = sD[0][2];
        #pragma unroll
        for (int n8 = 0; n8 < 8; n8++) {
            mxA = fmaxf(mxA, fmaxf(sD[n8][0], sD[n8][1]));
            mxB = fmaxf(mxB, fmaxf(sD[n8][2], sD[n8][3]));
        }
        mxA = fmaxf(mxA, __shfl_xor_sync(0xffffffffu, mxA, 1));
        mxA = fmaxf(mxA, __shfl_xor_sync(0xffffffffu, mxA, 2));
        mxB = fmaxf(mxB, __shfl_xor_sync(0xffffffffu, mxB, 1));
        mxB = fmaxf(mxB, __shfl_xor_sync(0xffffffffu, mxB, 2));

        float mnA = fmaxf(mA, mxA), mnB = fmaxf(mB, mxB);
        float corrA = __expf(mA - mnA), corrB = __expf(mB - mnB);

        float sumA = 0.0f, sumB = 0.0f;
        #pragma unroll
        for (int n8 = 0; n8 < 8; n8++) {
            float p0 = __expf(sD[n8][0] - mnA);
            float p1 = __expf(sD[n8][1] - mnA);
            float p2 = __expf(sD[n8][2] - mnB);
            float p3 = __expf(sD[n8][3] - mnB);
            sD[n8][0] = p0; sD[n8][1] = p1; sD[n8][2] = p2; sD[n8][3] = p3;
            sumA += p0 + p1; sumB += p2 + p3;
        }
        sumA += __shfl_xor_sync(0xffffffffu, sumA, 1);
        sumA += __shfl_xor_sync(0xffffffffu, sumA, 2);
        sumB += __shfl_xor_sync(0xffffffffu, sumB, 1);
        sumB += __shfl_xor_sync(0xffffffffu, sumB, 2);

        lA = lA * corrA + sumA; mA = mnA;
        lB = lB * corrB + sumB; mB = mnB;

        // rescale ctx, store P (warp-private rows) for PV A-frags
        #pragma unroll
        for (int n8 = 0; n8 < 8; n8++) {
            if (n8 < 4) {
                ctx[n8][0] *= corrA; ctx[n8][1] *= corrA;
                ctx[n8][2] *= corrB; ctx[n8][3] *= corrB;
            }
            *(float2*)(Ps + (16*w + g    )*PP + 8*n8 + 2*tig) = make_float2(sD[n8][0], sD[n8][1]);
            *(float2*)(Ps + (16*w + g + 8)*PP + 8*n8 + 2*tig) = make_float2(sD[n8][2], sD[n8][3]);
        }
        __syncwarp();

        // ---- ctx += P V (x3 tf32 split; P split at frag load) ----
        #pragma unroll
        for (int ks = 0; ks < 8; ks++) {
            float pa  = *(Ps + (16*w + g    )*PP + 8*ks + tig);
            float pb  = *(Ps + (16*w + g + 8)*PP + 8*ks + tig);
            float pa4 = *(Ps + (16*w + g    )*PP + 8*ks + tig + 4);
            float pb4 = *(Ps + (16*w + g + 8)*PP + 8*ks + tig + 4);
            uint32_t aH[4], aL[4];
            float h, l;
            split1(pa,  h, l); aH[0] = __float_as_uint(h); aL[0] = __float_as_uint(l);
            split1(pb,  h, l); aH[1] = __float_as_uint(h); aL[1] = __float_as_uint(l);
            split1(pa4, h, l); aH[2] = __float_as_uint(h); aL[2] = __float_as_uint(l);
            split1(pb4, h, l); aH[3] = __float_as_uint(h); aL[3] = __float_as_uint(l);
            #pragma unroll
            for (int n8 = 0; n8 < 4; n8++) {
                const float* vh0 = VsH + (8*ks + tig    )*VP + 8*n8 + g;
                const float* vh1 = VsH + (8*ks + tig + 4)*VP + 8*n8 + g;
                const float* vl0 = VsL + (8*ks + tig    )*VP + 8*n8 + g;
                const float* vl1 = VsL + (8*ks + tig + 4)*VP + 8*n8 + g;
                uint32_t bH[2] = { *(const uint32_t*)vh0, *(const uint32_t*)vh1 };
                uint32_t bL[2] = { *(const uint32_t*)vl0, *(const uint32_t*)vl1 };
                mma_tf32(ctx[n8], aH, bH);
                mma_tf32(ctx[n8], aL, bH);
                mma_tf32(ctx[n8], aH, bL);
            }
        }
    }

    // ---- final: ctx / l ----
    {
        float invA = 1.0f / lA;
        float invB = 1.0f / lB;
        float* o0 = out_ctx + ((size_t)bh * LSEQ + q0 + 16*w + g    ) * DVV;
        float* o1 = out_ctx + ((size_t)bh * LSEQ + q0 + 16*w + g + 8) * DVV;
        #pragma unroll
        for (int n8 = 0; n8 < 4; n8++) {
            *(float2*)(o0 + 8*n8 + 2*tig) = make_float2(ctx[n8][0]*invA, ctx[n8][1]*invA);
            *(float2*)(o1 + 8*n8 + 2*tig) = make_float2(ctx[n8][2]*invB, ctx[n8][3]*invB);
        }
    }
}

extern "C" void kernel_launch(void* const* d_in, const int* in_sizes, int n_in,
                              void* d_out, int out_size)
{
    (void)in_sizes; (void)n_in; (void)out_size;
    const float* Q  = (const float*)d_in[0];
    const float* K  = (const float*)d_in[1];
    const float* V  = (const float*)d_in[2];
    const int*   Mk = (const int*)d_in[3];
    const float* Rs = (const float*)d_in[4];

    float* out     = (float*)d_out;
    float* out_ctx = out;                                        // [B,H,L,DV]
    float* out_sc  = out + (size_t)BATCH * HEADS * LSEQ * DVV;   // [B,H,L,L]

    const size_t SMEM_BYTES = (size_t)(2*64*KP + 2*64*VP + BM*PP) * sizeof(float);
    cudaFuncSetAttribute((const void*)attn_tc_kernel,
                         cudaFuncAttributeMaxDynamicSharedMemorySize, (int)SMEM_BYTES);

    dim3 grid(LSEQ / BM, BATCH * HEADS);
    attn_tc_kernel<<<grid, NTH, SMEM_BYTES>>>(Q, K, V, Mk, Rs, out_ctx, out_sc);
}